// round 12
// baseline (speedup 1.0000x reference)
#include <cuda_runtime.h>
#include <cstdint>

// Locked config — measured best across 10 benched variants (55.6–56.0us ncu
// kernel time, reproducible). The problem is at the HBM mixed
// random-read/streaming-write floor: ~310MB DRAM traffic/launch (256MB
// compulsory writes + ~55MB gather misses against a 128MB table in 126MB L2)
// at ~5.5TB/s achieved. Every cache-policy, load/store-width, MLP and
// reduction variant measured neutral-to-worse with identical DRAM traffic.
// This round's single variable: 512-thread blocks (same warp count, fewer
// CTA scheduling events / wave transitions).
constexpr int EMBED = 256;
constexpr int BATCH = 64;
constexpr int BLOCK = 2048;
constexpr int NTOK  = BATCH * BLOCK;       // 131072 tokens
constexpr int VEC_PER_ROW = EMBED / 4;     // 64 float4 per row

__device__ __forceinline__ void stcs_f4(float4* p, float4 v) {
    // streaming store: evict-first in L2 (best-measured store policy)
    asm volatile("st.global.cs.v4.f32 [%0], {%1,%2,%3,%4};"
                 :: "l"(p), "f"(v.x), "f"(v.y), "f"(v.z), "f"(v.w) : "memory");
}

__global__ __launch_bounds__(512)
void embed_softmax_kernel(const int* __restrict__ idx,
                          const float* __restrict__ emb,
                          float* __restrict__ out) {
    const int warp = (blockIdx.x * blockDim.x + threadIdx.x) >> 5;
    const int lane = threadIdx.x & 31;
    if (warp >= NTOK) return;

    const int row = __ldg(idx + warp);
    const float4* __restrict__ src =
        reinterpret_cast<const float4*>(emb + (size_t)row * EMBED);

    // 64 float4 per row, 32 lanes -> 2 vec loads per lane (fully coalesced 1KB)
    float4 a = __ldg(src + lane);
    float4 b = __ldg(src + 32 + lane);

    float e0 = __expf(a.x), e1 = __expf(a.y), e2 = __expf(a.z), e3 = __expf(a.w);
    float e4 = __expf(b.x), e5 = __expf(b.y), e6 = __expf(b.z), e7 = __expf(b.w);

    float s = ((e0 + e1) + (e2 + e3)) + ((e4 + e5) + (e6 + e7));
    #pragma unroll
    for (int o = 16; o > 0; o >>= 1)
        s += __shfl_xor_sync(0xFFFFFFFFu, s, o);

    const float inv = __frcp_rn(s);

    float4* __restrict__ logit_dst =
        reinterpret_cast<float4*>(out) + (size_t)warp * VEC_PER_ROW;
    float4* __restrict__ prob_dst =
        logit_dst + (size_t)NTOK * VEC_PER_ROW;

    // logits: straight copy of gathered row
    stcs_f4(logit_dst + lane, a);
    stcs_f4(logit_dst + 32 + lane, b);

    // probs: exp * inv_sum
    stcs_f4(prob_dst + lane,      make_float4(e0 * inv, e1 * inv, e2 * inv, e3 * inv));
    stcs_f4(prob_dst + 32 + lane, make_float4(e4 * inv, e5 * inv, e6 * inv, e7 * inv));
}

extern "C" void kernel_launch(void* const* d_in, const int* in_sizes, int n_in,
                              void* d_out, int out_size) {
    const int* idx;
    const float* emb;
    if (in_sizes[0] == NTOK) {
        idx = (const int*)d_in[0];
        emb = (const float*)d_in[1];
    } else {
        idx = (const int*)d_in[1];
        emb = (const float*)d_in[0];
    }
    float* out = (float*)d_out;

    // one warp per token: 131072 warps -> 512-thread blocks, 16 warps each
    const int threads = 512;
    const int blocks = (NTOK * 32) / threads;  // 8192
    embed_softmax_kernel<<<blocks, threads>>>(idx, emb, out);
}

// round 13
// speedup vs baseline: 1.1021x; 1.1021x over previous
#include <cuda_runtime.h>
#include <cstdint>

// FINAL — measured best across 11 benched variants (55.6/56.0us ncu kernel
// time, reproduced twice). The kernel sits at the HBM mixed
// random-read/streaming-write floor: ~310MB DRAM/launch (256MB compulsory
// writes + ~55MB gather misses: 128MB table vs 126MB L2) at ~5.55TB/s.
// Closed axes: store policy (.cs best), load evict hints (all neutral/worse),
// v8 width (+2.5us), tokens/warp>1 (neutral), 512-thread blocks (+10us,
// L1tex queue choke), f32 redux (unsupported on sm_103).
constexpr int EMBED = 256;
constexpr int BATCH = 64;
constexpr int BLOCK = 2048;
constexpr int NTOK  = BATCH * BLOCK;       // 131072 tokens
constexpr int VEC_PER_ROW = EMBED / 4;     // 64 float4 per row

__device__ __forceinline__ void stcs_f4(float4* p, float4 v) {
    // streaming store: evict-first in L2 (best-measured store policy)
    asm volatile("st.global.cs.v4.f32 [%0], {%1,%2,%3,%4};"
                 :: "l"(p), "f"(v.x), "f"(v.y), "f"(v.z), "f"(v.w) : "memory");
}

__global__ __launch_bounds__(256)
void embed_softmax_kernel(const int* __restrict__ idx,
                          const float* __restrict__ emb,
                          float* __restrict__ out) {
    const int warp = (blockIdx.x * blockDim.x + threadIdx.x) >> 5;
    const int lane = threadIdx.x & 31;
    if (warp >= NTOK) return;

    const int row = __ldg(idx + warp);
    const float4* __restrict__ src =
        reinterpret_cast<const float4*>(emb + (size_t)row * EMBED);

    // 64 float4 per row, 32 lanes -> 2 vec loads per lane (fully coalesced 1KB)
    float4 a = __ldg(src + lane);
    float4 b = __ldg(src + 32 + lane);

    float e0 = __expf(a.x), e1 = __expf(a.y), e2 = __expf(a.z), e3 = __expf(a.w);
    float e4 = __expf(b.x), e5 = __expf(b.y), e6 = __expf(b.z), e7 = __expf(b.w);

    float s = ((e0 + e1) + (e2 + e3)) + ((e4 + e5) + (e6 + e7));
    #pragma unroll
    for (int o = 16; o > 0; o >>= 1)
        s += __shfl_xor_sync(0xFFFFFFFFu, s, o);

    const float inv = __frcp_rn(s);

    float4* __restrict__ logit_dst =
        reinterpret_cast<float4*>(out) + (size_t)warp * VEC_PER_ROW;
    float4* __restrict__ prob_dst =
        logit_dst + (size_t)NTOK * VEC_PER_ROW;

    // logits: straight copy of gathered row
    stcs_f4(logit_dst + lane, a);
    stcs_f4(logit_dst + 32 + lane, b);

    // probs: exp * inv_sum
    stcs_f4(prob_dst + lane,      make_float4(e0 * inv, e1 * inv, e2 * inv, e3 * inv));
    stcs_f4(prob_dst + 32 + lane, make_float4(e4 * inv, e5 * inv, e6 * inv, e7 * inv));
}

extern "C" void kernel_launch(void* const* d_in, const int* in_sizes, int n_in,
                              void* d_out, int out_size) {
    const int* idx;
    const float* emb;
    if (in_sizes[0] == NTOK) {
        idx = (const int*)d_in[0];
        emb = (const float*)d_in[1];
    } else {
        idx = (const int*)d_in[1];
        emb = (const float*)d_in[0];
    }
    float* out = (float*)d_out;

    // one warp per token: 131072 warps -> 256-thread blocks, 8 warps each
    const int threads = 256;
    const int blocks = (NTOK * 32) / threads;  // 16384
    embed_softmax_kernel<<<blocks, threads>>>(idx, emb, out);
}